// round 8
// baseline (speedup 1.0000x reference)
#include <cuda_runtime.h>
#include <cuda_bf16.h>
#include <cstdint>
#include <math.h>

#define BB 32
#define TT 4096
#define DIN 256
#define HID 512
#define AD 259
#define KLIFT 64
#define DMODEL 1024
#define KSEL 32
#define PGD_STEPS 60

// ---------------- scratch (device globals; no allocation allowed) ----------
__device__ float g_sal[BB * TT];
__device__ float g_spart[4][BB * TT];        // per-N-tile partial saliency dot
__device__ float g_xpart[16 * BB * DIN];
__device__ float g_xmean[BB * DIN];
__device__ float g_msal[BB];
__device__ int   g_topidx[BB * KSEL];
// W1 pre-fragmented for mma.sync B operand: [n_tile 64][k_chunk 16][lane 32]
__device__ uint2 g_BfH[64 * 16 * 32];
__device__ uint2 g_BfL[64 * 16 * 32];

__device__ __forceinline__ uint32_t pack_bf2(__nv_bfloat16 a, __nv_bfloat16 b) {
    return (uint32_t)__bfloat16_as_ushort(a) | ((uint32_t)__bfloat16_as_ushort(b) << 16);
}

// mma.sync m16n8k16 row.col f32.bf16.bf16.f32 (portable PTX, HMMA pipe)
__device__ __forceinline__ void mma_bf16(float* d, const uint32_t* a, const uint32_t* b) {
    asm volatile(
        "mma.sync.aligned.m16n8k16.row.col.f32.bf16.bf16.f32 "
        "{%0,%1,%2,%3}, {%4,%5,%6,%7}, {%8,%9}, {%0,%1,%2,%3};"
        : "+f"(d[0]), "+f"(d[1]), "+f"(d[2]), "+f"(d[3])
        : "r"(a[0]), "r"(a[1]), "r"(a[2]), "r"(a[3]), "r"(b[0]), "r"(b[1]));
}

// ldmatrix x4: loads 4 8x8 b16 matrices; lane supplies one 16B row address.
__device__ __forceinline__ void ldsm_x4(uint32_t* r, uint32_t saddr) {
    asm volatile(
        "ldmatrix.sync.aligned.m8n8.x4.shared.b16 {%0,%1,%2,%3}, [%4];"
        : "=r"(r[0]), "=r"(r[1]), "=r"(r[2]), "=r"(r[3]) : "r"(saddr));
}

__device__ __forceinline__ uint32_t smem_u32(const void* p) {
    return (uint32_t)__cvta_generic_to_shared(p);
}
// 16B-unit swizzle: distinct banks for all STS/LDSM phases
__device__ __forceinline__ uint32_t su16(uint32_t u) { return u ^ ((u >> 3) & 1u); }

// ---------------------------------------------------------------------------
// Kernel 0: W1 -> bf16 hi/lo in mma B-fragment order.
// ---------------------------------------------------------------------------
__global__ void k_convert_w(const float* __restrict__ W1)
{
    const int nt = blockIdx.x, kc = blockIdx.y, l = threadIdx.x;
    const int n = nt * 8 + (l >> 2);
    const int k = kc * 16 + (l & 3) * 2;
    float v00 = W1[(size_t)k * HID + n];
    float v01 = W1[(size_t)(k + 1) * HID + n];
    float v10 = W1[(size_t)(k + 8) * HID + n];
    float v11 = W1[(size_t)(k + 9) * HID + n];
    __nv_bfloat16 h00 = __float2bfloat16(v00), h01 = __float2bfloat16(v01);
    __nv_bfloat16 h10 = __float2bfloat16(v10), h11 = __float2bfloat16(v11);
    __nv_bfloat16 l00 = __float2bfloat16(v00 - __bfloat162float(h00));
    __nv_bfloat16 l01 = __float2bfloat16(v01 - __bfloat162float(h01));
    __nv_bfloat16 l10 = __float2bfloat16(v10 - __bfloat162float(h10));
    __nv_bfloat16 l11 = __float2bfloat16(v11 - __bfloat162float(h11));
    const int o = (nt * 16 + kc) * 32 + l;
    g_BfH[o] = make_uint2(pack_bf2(h00, h01), pack_bf2(h10, h11));
    g_BfL[o] = make_uint2(pack_bf2(l00, l01), pack_bf2(l10, l11));
}

// ---------------------------------------------------------------------------
// Kernel 1: bf16-split GEMM via mma.sync (AhBh + AlBh + AhBl)
// Warp tile m32n64: halves A-fragment LDSM traffic vs m64n32.
// grid (4, 1024): n-tile fastest -> x tiles L2-shared across the 4 n-CTAs.
// ---------------------------------------------------------------------------
__global__ __launch_bounds__(256, 2) void k_gemm_part(
    const float* __restrict__ x, const float* __restrict__ b1,
    const float* __restrict__ w_sal)
{
    __shared__ __align__(16) unsigned char sA[2][2][4096];
    __shared__ float part[2][128];
    __shared__ float sB1[128], sWs[128];

    const int tid = threadIdx.x;
    const int n0 = blockIdx.x * 128;    // 0..3
    const int m0 = blockIdx.y * 128;    // 0..1023
    const int lane = tid & 31, wid = tid >> 5;
    const int wm = (wid & 3) * 32;      // 4 warp rows
    const int wc = wid >> 2;            // 2 warp cols
    const int wn = wc * 64;
    const int g = lane >> 2, t = lane & 3;
    const int ntbase = (n0 >> 3) + wc * 8;

    if (tid < 128) { sB1[tid] = b1[n0 + tid]; sWs[tid] = w_sal[n0 + tid]; }

    const int arow = tid >> 1, ahalf = tid & 1;
    const uint32_t stsOff = su16((uint32_t)(arow * 2 + ahalf)) * 16;

    uint32_t frOff[2];
    {
        const int r8 = lane & 7, hr = (lane >> 3) & 1, hc = (lane >> 4) & 1;
#pragma unroll
        for (int mi = 0; mi < 2; mi++) {
            uint32_t row = (uint32_t)(wm + mi * 16 + hr * 8 + r8);
            frOff[mi] = su16(row * 2 + (uint32_t)hc) * 16;
        }
    }
    const uint32_t baseH[2] = {smem_u32(&sA[0][0][0]), smem_u32(&sA[1][0][0])};
    const uint32_t baseL[2] = {smem_u32(&sA[0][1][0]), smem_u32(&sA[1][1][0])};

    float acc[2][8][4];
#pragma unroll
    for (int mi = 0; mi < 2; mi++)
#pragma unroll
        for (int ni = 0; ni < 8; ni++)
#pragma unroll
            for (int q = 0; q < 4; q++) acc[mi][ni][q] = 0.f;

    float4 pa0, pa1;
    {
        const float* ap = &x[(size_t)(m0 + arow) * DIN + ahalf * 8];
        pa0 = *(const float4*)(ap);
        pa1 = *(const float4*)(ap + 4);
    }

    for (int s = 0; s < 16; s++) {
        const int buf = s & 1;
        // ---- B fragments: 8 n-tiles, hi+lo, coalesced LDG.64 from L2 ----
        uint32_t bh[8][2], bl[8][2];
#pragma unroll
        for (int ni = 0; ni < 8; ni++) {
            const int o = ((ntbase + ni) * 16 + s) * 32 + lane;
            uint2 vh = g_BfH[o];
            uint2 vl = g_BfL[o];
            bh[ni][0] = vh.x; bh[ni][1] = vh.y;
            bl[ni][0] = vl.x; bl[ni][1] = vl.y;
        }
        // ---- STS A (prefetched, split on the fly, swizzled) ----
        {
            float f[8] = {pa0.x, pa0.y, pa0.z, pa0.w, pa1.x, pa1.y, pa1.z, pa1.w};
            uint32_t hw[4], lw[4];
#pragma unroll
            for (int q = 0; q < 4; q++) {
                __nv_bfloat16 h0 = __float2bfloat16(f[q * 2]);
                __nv_bfloat16 h1 = __float2bfloat16(f[q * 2 + 1]);
                __nv_bfloat16 l0 = __float2bfloat16(f[q * 2] - __bfloat162float(h0));
                __nv_bfloat16 l1 = __float2bfloat16(f[q * 2 + 1] - __bfloat162float(h1));
                hw[q] = pack_bf2(h0, h1);
                lw[q] = pack_bf2(l0, l1);
            }
            *(uint4*)&sA[buf][0][stsOff] = make_uint4(hw[0], hw[1], hw[2], hw[3]);
            *(uint4*)&sA[buf][1][stsOff] = make_uint4(lw[0], lw[1], lw[2], lw[3]);
        }
        __syncthreads();
        if (s < 15) {
            const float* ap = &x[(size_t)(m0 + arow) * DIN + (s + 1) * 16 + ahalf * 8];
            pa0 = *(const float4*)(ap);
            pa1 = *(const float4*)(ap + 4);
        }

        uint32_t ah[2][4], al[2][4];
#pragma unroll
        for (int mi = 0; mi < 2; mi++) ldsm_x4(ah[mi], baseH[buf] + frOff[mi]);
#pragma unroll
        for (int mi = 0; mi < 2; mi++)
#pragma unroll
            for (int ni = 0; ni < 8; ni++)
                mma_bf16(acc[mi][ni], ah[mi], bh[ni]);
#pragma unroll
        for (int mi = 0; mi < 2; mi++)
#pragma unroll
            for (int ni = 0; ni < 8; ni++)
                mma_bf16(acc[mi][ni], ah[mi], bl[ni]);
#pragma unroll
        for (int mi = 0; mi < 2; mi++) ldsm_x4(al[mi], baseL[buf] + frOff[mi]);
#pragma unroll
        for (int mi = 0; mi < 2; mi++)
#pragma unroll
            for (int ni = 0; ni < 8; ni++)
                mma_bf16(acc[mi][ni], al[mi], bh[ni]);
        __syncthreads();
    }

    // ---- epilogue: tanh + w_sal dot over this warp's 64 columns ----
    float rsum[2][2];
    rsum[0][0] = rsum[0][1] = rsum[1][0] = rsum[1][1] = 0.f;
#pragma unroll
    for (int mi = 0; mi < 2; mi++)
#pragma unroll
        for (int ni = 0; ni < 8; ni++) {
            int c0 = wn + ni * 8 + t * 2;
            float w0 = sWs[c0], w1 = sWs[c0 + 1];
            float bb0 = sB1[c0], bb1 = sB1[c0 + 1];
            rsum[mi][0] += tanhf(acc[mi][ni][0] + bb0) * w0
                         + tanhf(acc[mi][ni][1] + bb1) * w1;
            rsum[mi][1] += tanhf(acc[mi][ni][2] + bb0) * w0
                         + tanhf(acc[mi][ni][3] + bb1) * w1;
        }
#pragma unroll
    for (int mi = 0; mi < 2; mi++)
#pragma unroll
        for (int sel = 0; sel < 2; sel++) {
            float v = rsum[mi][sel];
            v += __shfl_xor_sync(0xffffffffu, v, 1);
            v += __shfl_xor_sync(0xffffffffu, v, 2);
            if (t == 0) part[wc][wm + mi * 16 + sel * 8 + g] = v;
        }
    __syncthreads();
    if (tid < 128)
        g_spart[blockIdx.x][m0 + tid] = part[0][tid] + part[1][tid];
}

// ---------------------------------------------------------------------------
// Kernel 2a/2b: mean of x over T per batch (deterministic two-stage)
// ---------------------------------------------------------------------------
__global__ void k_xmean_part(const float* __restrict__ x)
{
    int b = blockIdx.x, ch = blockIdx.y, d = threadIdx.x;
    const float* base = x + ((size_t)b * TT + ch * 256) * DIN + d;
    float acc = 0.f;
    for (int t = 0; t < 256; t++) acc += base[(size_t)t * DIN];
    g_xpart[(ch * BB + b) * DIN + d] = acc;
}
__global__ void k_xmean_fin()
{
    int b = blockIdx.x, d = threadIdx.x;
    float acc = 0.f;
    for (int ch = 0; ch < 16; ch++) acc += g_xpart[(ch * BB + b) * DIN + d];
    g_xmean[b * DIN + d] = acc * (1.0f / TT);
}

// ---------------------------------------------------------------------------
// Kernel 3: fused sal-finalize + PGD selector (warm-started Newton tau,
// 1-sync block reduces), y_star out, mean_sal, exact top-32.
// ---------------------------------------------------------------------------
__global__ __launch_bounds__(1024) void k_selector(
    const float* __restrict__ b_sal, float* __restrict__ d_out)
{
    __shared__ float ysA[TT];
    __shared__ float ysB[TT];
    __shared__ float redS[2][32], redC[2][32];
    __shared__ float redT[2][32];
    __shared__ int   redi[2][32];

    const int b = blockIdx.x;
    const int tid = threadIdx.x;
    const int lane = tid & 31, wid = tid >> 5;
    const int i0 = tid * 4;

    float4 p0 = *(const float4*)&g_spart[0][b * TT + i0];
    float4 p1 = *(const float4*)&g_spart[1][b * TT + i0];
    float4 p2 = *(const float4*)&g_spart[2][b * TT + i0];
    float4 p3 = *(const float4*)&g_spart[3][b * TT + i0];
    const float bs = b_sal[0];
    float s[4];
    {
        float z0 = ((p0.x + p1.x) + p2.x) + p3.x + bs;
        float z1 = ((p0.y + p1.y) + p2.y) + p3.y + bs;
        float z2 = ((p0.z + p1.z) + p2.z) + p3.z + bs;
        float z3 = ((p0.w + p1.w) + p2.w) + p3.w + bs;
        s[0] = fmaxf(z0, 0.f) + log1pf(expf(-fabsf(z0)));
        s[1] = fmaxf(z1, 0.f) + log1pf(expf(-fabsf(z1)));
        s[2] = fmaxf(z2, 0.f) + log1pf(expf(-fabsf(z2)));
        s[3] = fmaxf(z3, 0.f) + log1pf(expf(-fabsf(z3)));
    }
    *(float4*)&g_sal[b * TT + i0] = make_float4(s[0], s[1], s[2], s[3]);

    float y[4] = {0.0078125f, 0.0078125f, 0.0078125f, 0.0078125f};
    ysA[i0] = y[0]; ysA[i0 + 1] = y[1]; ysA[i0 + 2] = y[2]; ysA[i0 + 3] = y[3];
    __syncthreads();

    float tau_prev = 0.f;
    for (int step = 0; step < PGD_STEPS; step++) {
        const float* rd = (step & 1) ? ysB : ysA;
        float*       wr = (step & 1) ? ysA : ysB;
        float l1 = (i0 > 0) ? rd[i0 - 1] : 0.f;
        float l2 = (i0 > 0) ? rd[i0 - 2] : 0.f;
        float r1 = (i0 + 4 < TT) ? rd[i0 + 4] : 0.f;
        float r2 = (i0 + 4 < TT) ? rd[i0 + 5] : 0.f;
        float nb[4];
        nb[0] = ((y[1] + l1) + y[2]) + l2;
        nb[1] = ((y[2] + y[0]) + y[3]) + l1;
        nb[2] = ((y[3] + y[1]) + r1) + y[0];
        nb[3] = ((r1 + y[2]) + r2) + y[1];

        float z[4];
#pragma unroll
        for (int q = 0; q < 4; q++) {
            float g = (s[q] - y[q]) - 0.5f * nb[q];
            z[q] = fminf(fmaxf(y[q] + 0.1f * g, 0.f), 1.f);
        }

        float tau = tau_prev;
        for (int it = 0; it < 24; it++) {
            const int p = it & 1;
            float ls = 0.f, lc = 0.f;
#pragma unroll
            for (int q = 0; q < 4; q++)
                if (z[q] > tau) { ls += z[q]; lc += 1.f; }
#pragma unroll
            for (int o = 16; o; o >>= 1) {
                ls += __shfl_xor_sync(0xffffffffu, ls, o);
                lc += __shfl_xor_sync(0xffffffffu, lc, o);
            }
            if (lane == 0) { redS[p][wid] = ls; redC[p][wid] = lc; }
            __syncthreads();
            float S = redS[p][lane], C = redC[p][lane];
#pragma unroll
            for (int o = 16; o; o >>= 1) {
                S += __shfl_xor_sync(0xffffffffu, S, o);
                C += __shfl_xor_sync(0xffffffffu, C, o);
            }
            float tnew = (C >= 1.f) ? fmaxf((S - 32.f) / C, 0.f) : 0.f;
            if (tnew == tau) break;
            tau = tnew;
        }
        tau_prev = tau;
#pragma unroll
        for (int q = 0; q < 4; q++)
            y[q] = fminf(fmaxf(z[q] - tau, 0.f), 1.f);
        wr[i0] = y[0]; wr[i0 + 1] = y[1]; wr[i0 + 2] = y[2]; wr[i0 + 3] = y[3];
        __syncthreads();
    }

    float* outY = d_out + (size_t)BB * KSEL * DMODEL + (size_t)b * TT;
    *(float4*)&outY[i0] = make_float4(y[0], y[1], y[2], y[3]);

    {
        float ms = ((s[0] + s[1]) + s[2]) + s[3];
#pragma unroll
        for (int o = 16; o; o >>= 1) ms += __shfl_xor_sync(0xffffffffu, ms, o);
        if (lane == 0) redS[0][wid] = ms;
        __syncthreads();
        if (tid < 32) {
            float v = redS[0][lane];
#pragma unroll
            for (int o = 16; o; o >>= 1) v += __shfl_xor_sync(0xffffffffu, v, o);
            if (lane == 0) g_msal[b] = v * (1.0f / TT);
        }
        __syncthreads();
    }

    float mval[4] = {y[0], y[1], y[2], y[3]};
    for (int sel = 0; sel < KSEL; sel++) {
        const int p = sel & 1;
        float bv = -1.f; int bi = TT;
#pragma unroll
        for (int q = 0; q < 4; q++)
            if (mval[q] > bv) { bv = mval[q]; bi = i0 + q; }
#pragma unroll
        for (int o = 16; o; o >>= 1) {
            float ov = __shfl_xor_sync(0xffffffffu, bv, o);
            int   oi = __shfl_xor_sync(0xffffffffu, bi, o);
            if (ov > bv || (ov == bv && oi < bi)) { bv = ov; bi = oi; }
        }
        if (lane == 0) { redT[p][wid] = bv; redi[p][wid] = bi; }
        __syncthreads();
        bv = redT[p][lane]; bi = redi[p][lane];
#pragma unroll
        for (int o = 16; o; o >>= 1) {
            float ov = __shfl_xor_sync(0xffffffffu, bv, o);
            int   oi = __shfl_xor_sync(0xffffffffu, bi, o);
            if (ov > bv || (ov == bv && oi < bi)) { bv = ov; bi = oi; }
        }
        if (tid == 0) g_topidx[b * KSEL + sel] = bi;
        if ((bi >> 2) == tid) mval[bi & 3] = -1.f;
    }
}

// ---------------------------------------------------------------------------
// Kernel 4: gather -> anchor vector -> lift (259->64) -> project (64->1024)
// ---------------------------------------------------------------------------
__global__ __launch_bounds__(256) void k_tokens(
    const float* __restrict__ x, const float* __restrict__ mu,
    const float* __restrict__ sigma, const float* __restrict__ W_lift,
    const float* __restrict__ b_lift, const float* __restrict__ W_proj,
    const float* __restrict__ b_proj, float* __restrict__ out)
{
    __shared__ float u[AD];
    __shared__ float lf[KLIFT];
    const int b = blockIdx.x, j = blockIdx.y;
    const int tid = threadIdx.x;
    const int idx = g_topidx[b * KSEL + j];

    {
        float v = x[((size_t)b * TT + idx) * DIN + tid] - g_xmean[b * DIN + tid];
        u[tid] = (v - mu[tid]) / sigma[tid];
    }
    if (tid == 0) {
        float sali = g_sal[b * TT + idx];
        float ms = g_msal[b];
        u[256] = ((sali - ms) - mu[256]) / sigma[256];
        float tn = (float)idx * (1.0f / 4096.0f);
        u[257] = ((tn - 0.4998779296875f) - mu[257]) / sigma[257];
        float ds = (idx == 0) ? 0.f : (sali - g_sal[b * TT + idx - 1]);
        float mds = (g_sal[b * TT + TT - 1] - g_sal[b * TT]) * (1.0f / 4096.0f);
        u[258] = ((ds - mds) - mu[258]) / sigma[258];
    }
    __syncthreads();

    if (tid < KLIFT) {
        float acc = b_lift[tid];
        for (int d = 0; d < AD; d++)
            acc = fmaf(u[d], W_lift[d * KLIFT + tid], acc);
        lf[tid] = acc;
    }
    __syncthreads();

    float* o = out + ((size_t)(b * KSEL + j)) * DMODEL;
    for (int m = tid; m < DMODEL; m += 256) {
        float acc = b_proj[m];
#pragma unroll
        for (int k = 0; k < KLIFT; k++)
            acc = fmaf(lf[k], W_proj[k * DMODEL + m], acc);
        o[m] = acc;
    }
}

// ---------------------------------------------------------------------------
extern "C" void kernel_launch(void* const* d_in, const int* in_sizes, int n_in,
                              void* d_out, int out_size)
{
    const float* x      = (const float*)d_in[0];
    const float* W1     = (const float*)d_in[1];
    const float* b1     = (const float*)d_in[2];
    const float* w_sal  = (const float*)d_in[5];
    const float* b_sal  = (const float*)d_in[6];
    const float* mu     = (const float*)d_in[7];
    const float* sigma  = (const float*)d_in[8];
    const float* W_lift = (const float*)d_in[9];
    const float* b_lift = (const float*)d_in[10];
    const float* W_proj = (const float*)d_in[11];
    const float* b_proj = (const float*)d_in[12];
    float* out = (float*)d_out;

    static cudaStream_t s2 = []() {
        cudaStream_t s; cudaStreamCreateWithFlags(&s, cudaStreamNonBlocking); return s;
    }();
    static cudaEvent_t evF = []() {
        cudaEvent_t e; cudaEventCreateWithFlags(&e, cudaEventDisableTiming); return e;
    }();
    static cudaEvent_t evJ = []() {
        cudaEvent_t e; cudaEventCreateWithFlags(&e, cudaEventDisableTiming); return e;
    }();

    cudaEventRecord(evF, 0);
    cudaStreamWaitEvent(s2, evF, 0);
    k_xmean_part<<<dim3(BB, 16), 256, 0, s2>>>(x);
    k_xmean_fin<<<BB, 256, 0, s2>>>();
    cudaEventRecord(evJ, s2);

    k_convert_w<<<dim3(64, 16), 32>>>(W1);
    k_gemm_part<<<dim3(4, 1024), 256>>>(x, b1, w_sal);
    k_selector<<<BB, 1024>>>(b_sal, out);

    cudaStreamWaitEvent(0, evJ, 0);
    k_tokens<<<dim3(BB, KSEL), 256>>>(x, mu, sigma, W_lift, b_lift, W_proj, b_proj, out);
}

// round 9
// speedup vs baseline: 1.0360x; 1.0360x over previous
#include <cuda_runtime.h>
#include <cuda_bf16.h>
#include <cstdint>
#include <math.h>

#define BB 32
#define TT 4096
#define DIN 256
#define HID 512
#define AD 259
#define KLIFT 64
#define DMODEL 1024
#define KSEL 32
#define PGD_STEPS 60

// ---------------- scratch (device globals; no allocation allowed) ----------
__device__ float g_sal[BB * TT];
__device__ float g_spart[4][BB * TT];        // per-N-tile partial saliency dot
__device__ float g_xpart[16 * BB * DIN];
__device__ float g_xmean[BB * DIN];
__device__ float g_msal[BB];
__device__ int   g_topidx[BB * KSEL];
// W1 pre-fragmented for mma.sync B operand: [n_tile 64][k_chunk 16][lane 32]
__device__ uint2 g_BfH[64 * 16 * 32];
__device__ uint2 g_BfL[64 * 16 * 32];

__device__ __forceinline__ uint32_t pack_bf2(__nv_bfloat16 a, __nv_bfloat16 b) {
    return (uint32_t)__bfloat16_as_ushort(a) | ((uint32_t)__bfloat16_as_ushort(b) << 16);
}

// mma.sync m16n8k16 row.col f32.bf16.bf16.f32 (portable PTX, HMMA pipe)
__device__ __forceinline__ void mma_bf16(float* d, const uint32_t* a, const uint32_t* b) {
    asm volatile(
        "mma.sync.aligned.m16n8k16.row.col.f32.bf16.bf16.f32 "
        "{%0,%1,%2,%3}, {%4,%5,%6,%7}, {%8,%9}, {%0,%1,%2,%3};"
        : "+f"(d[0]), "+f"(d[1]), "+f"(d[2]), "+f"(d[3])
        : "r"(a[0]), "r"(a[1]), "r"(a[2]), "r"(a[3]), "r"(b[0]), "r"(b[1]));
}

// ldmatrix x4: loads 4 8x8 b16 matrices; lane supplies one 16B row address.
__device__ __forceinline__ void ldsm_x4(uint32_t* r, uint32_t saddr) {
    asm volatile(
        "ldmatrix.sync.aligned.m8n8.x4.shared.b16 {%0,%1,%2,%3}, [%4];"
        : "=r"(r[0]), "=r"(r[1]), "=r"(r[2]), "=r"(r[3]) : "r"(saddr));
}

__device__ __forceinline__ uint32_t smem_u32(const void* p) {
    return (uint32_t)__cvta_generic_to_shared(p);
}
// 16B-unit swizzle: distinct banks for all STS/LDSM phases
__device__ __forceinline__ uint32_t su16(uint32_t u) { return u ^ ((u >> 3) & 1u); }

// ---------------------------------------------------------------------------
// Kernel 0: W1 -> bf16 hi/lo in mma B-fragment order.
// ---------------------------------------------------------------------------
__global__ void k_convert_w(const float* __restrict__ W1)
{
    const int nt = blockIdx.x, kc = blockIdx.y, l = threadIdx.x;
    const int n = nt * 8 + (l >> 2);
    const int k = kc * 16 + (l & 3) * 2;
    float v00 = W1[(size_t)k * HID + n];
    float v01 = W1[(size_t)(k + 1) * HID + n];
    float v10 = W1[(size_t)(k + 8) * HID + n];
    float v11 = W1[(size_t)(k + 9) * HID + n];
    __nv_bfloat16 h00 = __float2bfloat16(v00), h01 = __float2bfloat16(v01);
    __nv_bfloat16 h10 = __float2bfloat16(v10), h11 = __float2bfloat16(v11);
    __nv_bfloat16 l00 = __float2bfloat16(v00 - __bfloat162float(h00));
    __nv_bfloat16 l01 = __float2bfloat16(v01 - __bfloat162float(h01));
    __nv_bfloat16 l10 = __float2bfloat16(v10 - __bfloat162float(h10));
    __nv_bfloat16 l11 = __float2bfloat16(v11 - __bfloat162float(h11));
    const int o = (nt * 16 + kc) * 32 + l;
    g_BfH[o] = make_uint2(pack_bf2(h00, h01), pack_bf2(h10, h11));
    g_BfL[o] = make_uint2(pack_bf2(l00, l01), pack_bf2(l10, l11));
}

// ---------------------------------------------------------------------------
// Kernel 1: bf16-split GEMM via mma.sync (AhBh + AlBh + AhBl)
// R7 warp tile m64n32; n-fastest grid (x tiles L2-shared); COALESCED x loads:
// thread -> (row = tid>>2, 16B seg = tid&3): warp reads 8 rows x 64B contig.
// ---------------------------------------------------------------------------
__global__ __launch_bounds__(256, 2) void k_gemm_part(
    const float* __restrict__ x, const float* __restrict__ b1,
    const float* __restrict__ w_sal)
{
    __shared__ __align__(16) unsigned char sA[2][2][4096];
    __shared__ float part[4][128];
    __shared__ float sB1[128], sWs[128];

    const int tid = threadIdx.x;
    const int n0 = blockIdx.x * 128;    // n-tile fastest: 4 CTAs share x m-tile
    const int m0 = blockIdx.y * 128;
    const int lane = tid & 31, wid = tid >> 5;
    const int wm = (wid >> 2) * 64, wn = (wid & 3) * 32;
    const int g = lane >> 2, t = lane & 3;
    const int ntbase = (n0 >> 3) + ((wid & 3) * 4);

    if (tid < 128) { sB1[tid] = b1[n0 + tid]; sWs[tid] = w_sal[n0 + tid]; }

    // coalesced A mapping: each thread owns rows arow and arow+64, seg aseg
    const int arow = tid >> 2, aseg = tid & 3;
    const uint32_t offA = su16((uint32_t)(arow * 2 + (aseg >> 1))) * 16
                        + (uint32_t)(aseg & 1) * 8;
    const uint32_t offB = su16((uint32_t)((arow + 64) * 2 + (aseg >> 1))) * 16
                        + (uint32_t)(aseg & 1) * 8;

    uint32_t frOff[4];
    {
        const int r8 = lane & 7, hr = (lane >> 3) & 1, hc = (lane >> 4) & 1;
#pragma unroll
        for (int mi = 0; mi < 4; mi++) {
            uint32_t row = (uint32_t)(wm + mi * 16 + hr * 8 + r8);
            frOff[mi] = su16(row * 2 + (uint32_t)hc) * 16;
        }
    }
    const uint32_t baseH[2] = {smem_u32(&sA[0][0][0]), smem_u32(&sA[1][0][0])};
    const uint32_t baseL[2] = {smem_u32(&sA[0][1][0]), smem_u32(&sA[1][1][0])};

    float acc[4][4][4];
#pragma unroll
    for (int mi = 0; mi < 4; mi++)
#pragma unroll
        for (int ni = 0; ni < 4; ni++)
#pragma unroll
            for (int q = 0; q < 4; q++) acc[mi][ni][q] = 0.f;

    float4 pa0, pa1;
    pa0 = *(const float4*)&x[(size_t)(m0 + arow) * DIN + aseg * 4];
    pa1 = *(const float4*)&x[(size_t)(m0 + arow + 64) * DIN + aseg * 4];

    for (int s = 0; s < 16; s++) {
        const int buf = s & 1;
        // ---- B fragments for this chunk: coalesced LDG.64 from L2 ----
        uint2 fbh[4], fbl[4];
#pragma unroll
        for (int ni = 0; ni < 4; ni++) {
            const int o = ((ntbase + ni) * 16 + s) * 32 + lane;
            fbh[ni] = g_BfH[o];
            fbl[ni] = g_BfL[o];
        }
        // ---- STS A (prefetched, split on the fly, swizzled) ----
        {
            float f0[4] = {pa0.x, pa0.y, pa0.z, pa0.w};
            float f1[4] = {pa1.x, pa1.y, pa1.z, pa1.w};
            uint32_t h0[2], l0[2], h1[2], l1[2];
#pragma unroll
            for (int q = 0; q < 2; q++) {
                __nv_bfloat16 a0 = __float2bfloat16(f0[q * 2]);
                __nv_bfloat16 a1 = __float2bfloat16(f0[q * 2 + 1]);
                h0[q] = pack_bf2(a0, a1);
                l0[q] = pack_bf2(__float2bfloat16(f0[q * 2] - __bfloat162float(a0)),
                                 __float2bfloat16(f0[q * 2 + 1] - __bfloat162float(a1)));
                __nv_bfloat16 b0 = __float2bfloat16(f1[q * 2]);
                __nv_bfloat16 b1v = __float2bfloat16(f1[q * 2 + 1]);
                h1[q] = pack_bf2(b0, b1v);
                l1[q] = pack_bf2(__float2bfloat16(f1[q * 2] - __bfloat162float(b0)),
                                 __float2bfloat16(f1[q * 2 + 1] - __bfloat162float(b1v)));
            }
            *(uint2*)&sA[buf][0][offA] = make_uint2(h0[0], h0[1]);
            *(uint2*)&sA[buf][1][offA] = make_uint2(l0[0], l0[1]);
            *(uint2*)&sA[buf][0][offB] = make_uint2(h1[0], h1[1]);
            *(uint2*)&sA[buf][1][offB] = make_uint2(l1[0], l1[1]);
        }
        __syncthreads();
        if (s < 15) {
            pa0 = *(const float4*)&x[(size_t)(m0 + arow) * DIN + (s + 1) * 16 + aseg * 4];
            pa1 = *(const float4*)&x[(size_t)(m0 + arow + 64) * DIN + (s + 1) * 16 + aseg * 4];
        }

        uint32_t bh[4][2], bl[4][2];
#pragma unroll
        for (int ni = 0; ni < 4; ni++) {
            bh[ni][0] = fbh[ni].x; bh[ni][1] = fbh[ni].y;
            bl[ni][0] = fbl[ni].x; bl[ni][1] = fbl[ni].y;
        }
        uint32_t ah[4][4], al[4][4];
#pragma unroll
        for (int mi = 0; mi < 4; mi++) ldsm_x4(ah[mi], baseH[buf] + frOff[mi]);
#pragma unroll
        for (int mi = 0; mi < 4; mi++)
#pragma unroll
            for (int ni = 0; ni < 4; ni++)
                mma_bf16(acc[mi][ni], ah[mi], bh[ni]);
#pragma unroll
        for (int mi = 0; mi < 4; mi++)
#pragma unroll
            for (int ni = 0; ni < 4; ni++)
                mma_bf16(acc[mi][ni], ah[mi], bl[ni]);
#pragma unroll
        for (int mi = 0; mi < 4; mi++) ldsm_x4(al[mi], baseL[buf] + frOff[mi]);
#pragma unroll
        for (int mi = 0; mi < 4; mi++)
#pragma unroll
            for (int ni = 0; ni < 4; ni++)
                mma_bf16(acc[mi][ni], al[mi], bh[ni]);
        __syncthreads();
    }

    // ---- epilogue: tanh + w_sal dot over this CTA's 128 columns ----
    float rsum[4][2];
#pragma unroll
    for (int mi = 0; mi < 4; mi++) { rsum[mi][0] = 0.f; rsum[mi][1] = 0.f; }
#pragma unroll
    for (int mi = 0; mi < 4; mi++)
#pragma unroll
        for (int ni = 0; ni < 4; ni++) {
            int c0 = wn + ni * 8 + t * 2;
            float w0 = sWs[c0], w1 = sWs[c0 + 1];
            float bb0 = sB1[c0], bb1 = sB1[c0 + 1];
            rsum[mi][0] += tanhf(acc[mi][ni][0] + bb0) * w0
                         + tanhf(acc[mi][ni][1] + bb1) * w1;
            rsum[mi][1] += tanhf(acc[mi][ni][2] + bb0) * w0
                         + tanhf(acc[mi][ni][3] + bb1) * w1;
        }
#pragma unroll
    for (int mi = 0; mi < 4; mi++)
#pragma unroll
        for (int sel = 0; sel < 2; sel++) {
            float v = rsum[mi][sel];
            v += __shfl_xor_sync(0xffffffffu, v, 1);
            v += __shfl_xor_sync(0xffffffffu, v, 2);
            if (t == 0) part[wid & 3][wm + mi * 16 + sel * 8 + g] = v;
        }
    __syncthreads();
    if (tid < 128) {
        float v = ((part[0][tid] + part[1][tid]) + part[2][tid]) + part[3][tid];
        g_spart[blockIdx.x][m0 + tid] = v;
    }
}

// ---------------------------------------------------------------------------
// Kernel 2a/2b: mean of x over T per batch (deterministic two-stage)
// ---------------------------------------------------------------------------
__global__ void k_xmean_part(const float* __restrict__ x)
{
    int b = blockIdx.x, ch = blockIdx.y, d = threadIdx.x;
    const float* base = x + ((size_t)b * TT + ch * 256) * DIN + d;
    float acc = 0.f;
    for (int t = 0; t < 256; t++) acc += base[(size_t)t * DIN];
    g_xpart[(ch * BB + b) * DIN + d] = acc;
}
__global__ void k_xmean_fin()
{
    int b = blockIdx.x, d = threadIdx.x;
    float acc = 0.f;
    for (int ch = 0; ch < 16; ch++) acc += g_xpart[(ch * BB + b) * DIN + d];
    g_xmean[b * DIN + d] = acc * (1.0f / TT);
}

// ---------------------------------------------------------------------------
// Kernel 3: fused sal-finalize + PGD selector (warm-started Newton tau,
// 1-sync block reduces), y_star out, mean_sal, exact top-32.
// ---------------------------------------------------------------------------
__global__ __launch_bounds__(1024) void k_selector(
    const float* __restrict__ b_sal, float* __restrict__ d_out)
{
    __shared__ float ysA[TT];
    __shared__ float ysB[TT];
    __shared__ float redS[2][32], redC[2][32];
    __shared__ float redT[2][32];
    __shared__ int   redi[2][32];

    const int b = blockIdx.x;
    const int tid = threadIdx.x;
    const int lane = tid & 31, wid = tid >> 5;
    const int i0 = tid * 4;

    float4 p0 = *(const float4*)&g_spart[0][b * TT + i0];
    float4 p1 = *(const float4*)&g_spart[1][b * TT + i0];
    float4 p2 = *(const float4*)&g_spart[2][b * TT + i0];
    float4 p3 = *(const float4*)&g_spart[3][b * TT + i0];
    const float bs = b_sal[0];
    float s[4];
    {
        float z0 = ((p0.x + p1.x) + p2.x) + p3.x + bs;
        float z1 = ((p0.y + p1.y) + p2.y) + p3.y + bs;
        float z2 = ((p0.z + p1.z) + p2.z) + p3.z + bs;
        float z3 = ((p0.w + p1.w) + p2.w) + p3.w + bs;
        s[0] = fmaxf(z0, 0.f) + log1pf(expf(-fabsf(z0)));
        s[1] = fmaxf(z1, 0.f) + log1pf(expf(-fabsf(z1)));
        s[2] = fmaxf(z2, 0.f) + log1pf(expf(-fabsf(z2)));
        s[3] = fmaxf(z3, 0.f) + log1pf(expf(-fabsf(z3)));
    }
    *(float4*)&g_sal[b * TT + i0] = make_float4(s[0], s[1], s[2], s[3]);

    float y[4] = {0.0078125f, 0.0078125f, 0.0078125f, 0.0078125f};
    ysA[i0] = y[0]; ysA[i0 + 1] = y[1]; ysA[i0 + 2] = y[2]; ysA[i0 + 3] = y[3];
    __syncthreads();

    float tau_prev = 0.f;
    for (int step = 0; step < PGD_STEPS; step++) {
        const float* rd = (step & 1) ? ysB : ysA;
        float*       wr = (step & 1) ? ysA : ysB;
        float l1 = (i0 > 0) ? rd[i0 - 1] : 0.f;
        float l2 = (i0 > 0) ? rd[i0 - 2] : 0.f;
        float r1 = (i0 + 4 < TT) ? rd[i0 + 4] : 0.f;
        float r2 = (i0 + 4 < TT) ? rd[i0 + 5] : 0.f;
        float nb[4];
        nb[0] = ((y[1] + l1) + y[2]) + l2;
        nb[1] = ((y[2] + y[0]) + y[3]) + l1;
        nb[2] = ((y[3] + y[1]) + r1) + y[0];
        nb[3] = ((r1 + y[2]) + r2) + y[1];

        float z[4];
#pragma unroll
        for (int q = 0; q < 4; q++) {
            float g = (s[q] - y[q]) - 0.5f * nb[q];
            z[q] = fminf(fmaxf(y[q] + 0.1f * g, 0.f), 1.f);
        }

        float tau = tau_prev;
        for (int it = 0; it < 24; it++) {
            const int p = it & 1;
            float ls = 0.f, lc = 0.f;
#pragma unroll
            for (int q = 0; q < 4; q++)
                if (z[q] > tau) { ls += z[q]; lc += 1.f; }
#pragma unroll
            for (int o = 16; o; o >>= 1) {
                ls += __shfl_xor_sync(0xffffffffu, ls, o);
                lc += __shfl_xor_sync(0xffffffffu, lc, o);
            }
            if (lane == 0) { redS[p][wid] = ls; redC[p][wid] = lc; }
            __syncthreads();
            float S = redS[p][lane], C = redC[p][lane];
#pragma unroll
            for (int o = 16; o; o >>= 1) {
                S += __shfl_xor_sync(0xffffffffu, S, o);
                C += __shfl_xor_sync(0xffffffffu, C, o);
            }
            float tnew = (C >= 1.f) ? fmaxf((S - 32.f) / C, 0.f) : 0.f;
            if (tnew == tau) break;
            tau = tnew;
        }
        tau_prev = tau;
#pragma unroll
        for (int q = 0; q < 4; q++)
            y[q] = fminf(fmaxf(z[q] - tau, 0.f), 1.f);
        wr[i0] = y[0]; wr[i0 + 1] = y[1]; wr[i0 + 2] = y[2]; wr[i0 + 3] = y[3];
        __syncthreads();
    }

    float* outY = d_out + (size_t)BB * KSEL * DMODEL + (size_t)b * TT;
    *(float4*)&outY[i0] = make_float4(y[0], y[1], y[2], y[3]);

    {
        float ms = ((s[0] + s[1]) + s[2]) + s[3];
#pragma unroll
        for (int o = 16; o; o >>= 1) ms += __shfl_xor_sync(0xffffffffu, ms, o);
        if (lane == 0) redS[0][wid] = ms;
        __syncthreads();
        if (tid < 32) {
            float v = redS[0][lane];
#pragma unroll
            for (int o = 16; o; o >>= 1) v += __shfl_xor_sync(0xffffffffu, v, o);
            if (lane == 0) g_msal[b] = v * (1.0f / TT);
        }
        __syncthreads();
    }

    float mval[4] = {y[0], y[1], y[2], y[3]};
    for (int sel = 0; sel < KSEL; sel++) {
        const int p = sel & 1;
        float bv = -1.f; int bi = TT;
#pragma unroll
        for (int q = 0; q < 4; q++)
            if (mval[q] > bv) { bv = mval[q]; bi = i0 + q; }
#pragma unroll
        for (int o = 16; o; o >>= 1) {
            float ov = __shfl_xor_sync(0xffffffffu, bv, o);
            int   oi = __shfl_xor_sync(0xffffffffu, bi, o);
            if (ov > bv || (ov == bv && oi < bi)) { bv = ov; bi = oi; }
        }
        if (lane == 0) { redT[p][wid] = bv; redi[p][wid] = bi; }
        __syncthreads();
        bv = redT[p][lane]; bi = redi[p][lane];
#pragma unroll
        for (int o = 16; o; o >>= 1) {
            float ov = __shfl_xor_sync(0xffffffffu, bv, o);
            int   oi = __shfl_xor_sync(0xffffffffu, bi, o);
            if (ov > bv || (ov == bv && oi < bi)) { bv = ov; bi = oi; }
        }
        if (tid == 0) g_topidx[b * KSEL + sel] = bi;
        if ((bi >> 2) == tid) mval[bi & 3] = -1.f;
    }
}

// ---------------------------------------------------------------------------
// Kernel 4: gather -> anchor vector -> lift (259->64) -> project (64->1024)
// ---------------------------------------------------------------------------
__global__ __launch_bounds__(256) void k_tokens(
    const float* __restrict__ x, const float* __restrict__ mu,
    const float* __restrict__ sigma, const float* __restrict__ W_lift,
    const float* __restrict__ b_lift, const float* __restrict__ W_proj,
    const float* __restrict__ b_proj, float* __restrict__ out)
{
    __shared__ float u[AD];
    __shared__ float lf[KLIFT];
    const int b = blockIdx.x, j = blockIdx.y;
    const int tid = threadIdx.x;
    const int idx = g_topidx[b * KSEL + j];

    {
        float v = x[((size_t)b * TT + idx) * DIN + tid] - g_xmean[b * DIN + tid];
        u[tid] = (v - mu[tid]) / sigma[tid];
    }
    if (tid == 0) {
        float sali = g_sal[b * TT + idx];
        float ms = g_msal[b];
        u[256] = ((sali - ms) - mu[256]) / sigma[256];
        float tn = (float)idx * (1.0f / 4096.0f);
        u[257] = ((tn - 0.4998779296875f) - mu[257]) / sigma[257];
        float ds = (idx == 0) ? 0.f : (sali - g_sal[b * TT + idx - 1]);
        float mds = (g_sal[b * TT + TT - 1] - g_sal[b * TT]) * (1.0f / 4096.0f);
        u[258] = ((ds - mds) - mu[258]) / sigma[258];
    }
    __syncthreads();

    if (tid < KLIFT) {
        float acc = b_lift[tid];
        for (int d = 0; d < AD; d++)
            acc = fmaf(u[d], W_lift[d * KLIFT + tid], acc);
        lf[tid] = acc;
    }
    __syncthreads();

    float* o = out + ((size_t)(b * KSEL + j)) * DMODEL;
    for (int m = tid; m < DMODEL; m += 256) {
        float acc = b_proj[m];
#pragma unroll
        for (int k = 0; k < KLIFT; k++)
            acc = fmaf(lf[k], W_proj[k * DMODEL + m], acc);
        o[m] = acc;
    }
}

// ---------------------------------------------------------------------------
extern "C" void kernel_launch(void* const* d_in, const int* in_sizes, int n_in,
                              void* d_out, int out_size)
{
    const float* x      = (const float*)d_in[0];
    const float* W1     = (const float*)d_in[1];
    const float* b1     = (const float*)d_in[2];
    const float* w_sal  = (const float*)d_in[5];
    const float* b_sal  = (const float*)d_in[6];
    const float* mu     = (const float*)d_in[7];
    const float* sigma  = (const float*)d_in[8];
    const float* W_lift = (const float*)d_in[9];
    const float* b_lift = (const float*)d_in[10];
    const float* W_proj = (const float*)d_in[11];
    const float* b_proj = (const float*)d_in[12];
    float* out = (float*)d_out;

    static cudaStream_t s2 = []() {
        cudaStream_t s; cudaStreamCreateWithFlags(&s, cudaStreamNonBlocking); return s;
    }();
    static cudaEvent_t evF = []() {
        cudaEvent_t e; cudaEventCreateWithFlags(&e, cudaEventDisableTiming); return e;
    }();
    static cudaEvent_t evJ = []() {
        cudaEvent_t e; cudaEventCreateWithFlags(&e, cudaEventDisableTiming); return e;
    }();

    cudaEventRecord(evF, 0);
    cudaStreamWaitEvent(s2, evF, 0);
    k_xmean_part<<<dim3(BB, 16), 256, 0, s2>>>(x);
    k_xmean_fin<<<BB, 256, 0, s2>>>();
    cudaEventRecord(evJ, s2);

    k_convert_w<<<dim3(64, 16), 32>>>(W1);
    k_gemm_part<<<dim3(4, 1024), 256>>>(x, b1, w_sal);
    k_selector<<<BB, 1024>>>(b_sal, out);

    cudaStreamWaitEvent(0, evJ, 0);
    k_tokens<<<dim3(BB, KSEL), 256>>>(x, mu, sigma, W_lift, b_lift, W_proj, b_proj, out);
}

// round 10
// speedup vs baseline: 1.0817x; 1.0441x over previous
#include <cuda_runtime.h>
#include <cuda_bf16.h>
#include <cstdint>
#include <math.h>

#define BB 32
#define TT 4096
#define DIN 256
#define HID 512
#define AD 259
#define KLIFT 64
#define DMODEL 1024
#define KSEL 32
#define PGD_STEPS 60

// ---------------- scratch (device globals; no allocation allowed) ----------
__device__ float g_sal[BB * TT];
__device__ float g_spart[4][BB * TT];        // per-N-tile partial saliency dot
__device__ float g_xpart[16 * BB * DIN];
__device__ float g_xmean[BB * DIN];
__device__ float g_msal[BB];
__device__ int   g_topidx[BB * KSEL];
// W1 pre-fragmented for mma.sync B operand: [n_tile 64][k_chunk 16][lane 32]
__device__ uint2 g_BfH[64 * 16 * 32];
__device__ uint2 g_BfL[64 * 16 * 32];

__device__ __forceinline__ uint32_t pack_bf2(__nv_bfloat16 a, __nv_bfloat16 b) {
    return (uint32_t)__bfloat16_as_ushort(a) | ((uint32_t)__bfloat16_as_ushort(b) << 16);
}

// mma.sync m16n8k16 row.col f32.bf16.bf16.f32 (portable PTX, HMMA pipe)
__device__ __forceinline__ void mma_bf16(float* d, const uint32_t* a, const uint32_t* b) {
    asm volatile(
        "mma.sync.aligned.m16n8k16.row.col.f32.bf16.bf16.f32 "
        "{%0,%1,%2,%3}, {%4,%5,%6,%7}, {%8,%9}, {%0,%1,%2,%3};"
        : "+f"(d[0]), "+f"(d[1]), "+f"(d[2]), "+f"(d[3])
        : "r"(a[0]), "r"(a[1]), "r"(a[2]), "r"(a[3]), "r"(b[0]), "r"(b[1]));
}

// ldmatrix x4: loads 4 8x8 b16 matrices; lane supplies one 16B row address.
__device__ __forceinline__ void ldsm_x4(uint32_t* r, uint32_t saddr) {
    asm volatile(
        "ldmatrix.sync.aligned.m8n8.x4.shared.b16 {%0,%1,%2,%3}, [%4];"
        : "=r"(r[0]), "=r"(r[1]), "=r"(r[2]), "=r"(r[3]) : "r"(saddr));
}

__device__ __forceinline__ uint32_t smem_u32(const void* p) {
    return (uint32_t)__cvta_generic_to_shared(p);
}
// 16B-unit swizzle: distinct banks for all STS/LDSM phases
__device__ __forceinline__ uint32_t su16(uint32_t u) { return u ^ ((u >> 3) & 1u); }

// trunc-split of a float4 into bf16 hi (2 PRMT) + lo (2 FADD-pairs + cvt.bf16x2)
__device__ __forceinline__ void split4(float4 v, uint2* hi, uint2* lo) {
    uint32_t b0 = __float_as_uint(v.x), b1 = __float_as_uint(v.y);
    uint32_t b2 = __float_as_uint(v.z), b3 = __float_as_uint(v.w);
    hi->x = __byte_perm(b0, b1, 0x7632);
    hi->y = __byte_perm(b2, b3, 0x7632);
    float l0 = v.x - __uint_as_float(b0 & 0xFFFF0000u);
    float l1 = v.y - __uint_as_float(b1 & 0xFFFF0000u);
    float l2 = v.z - __uint_as_float(b2 & 0xFFFF0000u);
    float l3 = v.w - __uint_as_float(b3 & 0xFFFF0000u);
    __nv_bfloat162 p0 = __float22bfloat162_rn(make_float2(l0, l1));
    __nv_bfloat162 p1 = __float22bfloat162_rn(make_float2(l2, l3));
    lo->x = *(uint32_t*)&p0;
    lo->y = *(uint32_t*)&p1;
}

// ---------------------------------------------------------------------------
// Kernel 0: W1 -> bf16 hi/lo (RNE) in mma B-fragment order.
// ---------------------------------------------------------------------------
__global__ void k_convert_w(const float* __restrict__ W1)
{
    const int nt = blockIdx.x, kc = blockIdx.y, l = threadIdx.x;
    const int n = nt * 8 + (l >> 2);
    const int k = kc * 16 + (l & 3) * 2;
    float v00 = W1[(size_t)k * HID + n];
    float v01 = W1[(size_t)(k + 1) * HID + n];
    float v10 = W1[(size_t)(k + 8) * HID + n];
    float v11 = W1[(size_t)(k + 9) * HID + n];
    __nv_bfloat16 h00 = __float2bfloat16(v00), h01 = __float2bfloat16(v01);
    __nv_bfloat16 h10 = __float2bfloat16(v10), h11 = __float2bfloat16(v11);
    __nv_bfloat16 l00 = __float2bfloat16(v00 - __bfloat162float(h00));
    __nv_bfloat16 l01 = __float2bfloat16(v01 - __bfloat162float(h01));
    __nv_bfloat16 l10 = __float2bfloat16(v10 - __bfloat162float(h10));
    __nv_bfloat16 l11 = __float2bfloat16(v11 - __bfloat162float(h11));
    const int o = (nt * 16 + kc) * 32 + l;
    g_BfH[o] = make_uint2(pack_bf2(h00, h01), pack_bf2(h10, h11));
    g_BfL[o] = make_uint2(pack_bf2(l00, l01), pack_bf2(l10, l11));
}

// ---------------------------------------------------------------------------
// Kernel 1: bf16-split GEMM via mma.sync (AhBh + AlBh + AhBl)
// m64n32 warp tile; n-fastest grid; coalesced x loads; trunc-split (PRMT);
// single barrier per mainloop iteration (double-buffer proof).
// ---------------------------------------------------------------------------
__global__ __launch_bounds__(256, 2) void k_gemm_part(
    const float* __restrict__ x, const float* __restrict__ b1,
    const float* __restrict__ w_sal)
{
    __shared__ __align__(16) unsigned char sA[2][2][4096];
    __shared__ float part[4][128];
    __shared__ float sB1[128], sWs[128];

    const int tid = threadIdx.x;
    const int n0 = blockIdx.x * 128;    // n-tile fastest: 4 CTAs share x m-tile
    const int m0 = blockIdx.y * 128;
    const int lane = tid & 31, wid = tid >> 5;
    const int wm = (wid >> 2) * 64, wn = (wid & 3) * 32;
    const int g = lane >> 2, t = lane & 3;
    const int ntbase = (n0 >> 3) + ((wid & 3) * 4);

    if (tid < 128) { sB1[tid] = b1[n0 + tid]; sWs[tid] = w_sal[n0 + tid]; }

    // coalesced A mapping: each thread owns rows arow and arow+64, seg aseg
    const int arow = tid >> 2, aseg = tid & 3;
    const uint32_t offA = su16((uint32_t)(arow * 2 + (aseg >> 1))) * 16
                        + (uint32_t)(aseg & 1) * 8;
    const uint32_t offB = su16((uint32_t)((arow + 64) * 2 + (aseg >> 1))) * 16
                        + (uint32_t)(aseg & 1) * 8;

    uint32_t frOff[4];
    {
        const int r8 = lane & 7, hr = (lane >> 3) & 1, hc = (lane >> 4) & 1;
#pragma unroll
        for (int mi = 0; mi < 4; mi++) {
            uint32_t row = (uint32_t)(wm + mi * 16 + hr * 8 + r8);
            frOff[mi] = su16(row * 2 + (uint32_t)hc) * 16;
        }
    }
    const uint32_t baseH[2] = {smem_u32(&sA[0][0][0]), smem_u32(&sA[1][0][0])};
    const uint32_t baseL[2] = {smem_u32(&sA[0][1][0]), smem_u32(&sA[1][1][0])};

    float acc[4][4][4];
#pragma unroll
    for (int mi = 0; mi < 4; mi++)
#pragma unroll
        for (int ni = 0; ni < 4; ni++)
#pragma unroll
            for (int q = 0; q < 4; q++) acc[mi][ni][q] = 0.f;

    float4 pa0, pa1;
    pa0 = *(const float4*)&x[(size_t)(m0 + arow) * DIN + aseg * 4];
    pa1 = *(const float4*)&x[(size_t)(m0 + arow + 64) * DIN + aseg * 4];

    for (int s = 0; s < 16; s++) {
        const int buf = s & 1;
        // ---- B fragments for this chunk: coalesced LDG.64 from L2 ----
        uint2 fbh[4], fbl[4];
#pragma unroll
        for (int ni = 0; ni < 4; ni++) {
            const int o = ((ntbase + ni) * 16 + s) * 32 + lane;
            fbh[ni] = g_BfH[o];
            fbl[ni] = g_BfL[o];
        }
        // ---- STS A (prefetched, trunc-split, swizzled) ----
        {
            uint2 h0, l0, h1, l1;
            split4(pa0, &h0, &l0);
            split4(pa1, &h1, &l1);
            *(uint2*)&sA[buf][0][offA] = h0;
            *(uint2*)&sA[buf][1][offA] = l0;
            *(uint2*)&sA[buf][0][offB] = h1;
            *(uint2*)&sA[buf][1][offB] = l1;
        }
        __syncthreads();   // single barrier per iteration (double buffer)
        if (s < 15) {
            pa0 = *(const float4*)&x[(size_t)(m0 + arow) * DIN + (s + 1) * 16 + aseg * 4];
            pa1 = *(const float4*)&x[(size_t)(m0 + arow + 64) * DIN + (s + 1) * 16 + aseg * 4];
        }

        uint32_t bh[4][2], bl[4][2];
#pragma unroll
        for (int ni = 0; ni < 4; ni++) {
            bh[ni][0] = fbh[ni].x; bh[ni][1] = fbh[ni].y;
            bl[ni][0] = fbl[ni].x; bl[ni][1] = fbl[ni].y;
        }
        uint32_t ah[4][4], al[4][4];
#pragma unroll
        for (int mi = 0; mi < 4; mi++) ldsm_x4(ah[mi], baseH[buf] + frOff[mi]);
#pragma unroll
        for (int mi = 0; mi < 4; mi++)
#pragma unroll
            for (int ni = 0; ni < 4; ni++)
                mma_bf16(acc[mi][ni], ah[mi], bh[ni]);
#pragma unroll
        for (int mi = 0; mi < 4; mi++)
#pragma unroll
            for (int ni = 0; ni < 4; ni++)
                mma_bf16(acc[mi][ni], ah[mi], bl[ni]);
#pragma unroll
        for (int mi = 0; mi < 4; mi++) ldsm_x4(al[mi], baseL[buf] + frOff[mi]);
#pragma unroll
        for (int mi = 0; mi < 4; mi++)
#pragma unroll
            for (int ni = 0; ni < 4; ni++)
                mma_bf16(acc[mi][ni], al[mi], bh[ni]);
    }

    // ---- epilogue: tanh + w_sal dot over this CTA's 128 columns ----
    float rsum[4][2];
#pragma unroll
    for (int mi = 0; mi < 4; mi++) { rsum[mi][0] = 0.f; rsum[mi][1] = 0.f; }
#pragma unroll
    for (int mi = 0; mi < 4; mi++)
#pragma unroll
        for (int ni = 0; ni < 4; ni++) {
            int c0 = wn + ni * 8 + t * 2;
            float w0 = sWs[c0], w1 = sWs[c0 + 1];
            float bb0 = sB1[c0], bb1 = sB1[c0 + 1];
            rsum[mi][0] += tanhf(acc[mi][ni][0] + bb0) * w0
                         + tanhf(acc[mi][ni][1] + bb1) * w1;
            rsum[mi][1] += tanhf(acc[mi][ni][2] + bb0) * w0
                         + tanhf(acc[mi][ni][3] + bb1) * w1;
        }
#pragma unroll
    for (int mi = 0; mi < 4; mi++)
#pragma unroll
        for (int sel = 0; sel < 2; sel++) {
            float v = rsum[mi][sel];
            v += __shfl_xor_sync(0xffffffffu, v, 1);
            v += __shfl_xor_sync(0xffffffffu, v, 2);
            if (t == 0) part[wid & 3][wm + mi * 16 + sel * 8 + g] = v;
        }
    __syncthreads();
    if (tid < 128) {
        float v = ((part[0][tid] + part[1][tid]) + part[2][tid]) + part[3][tid];
        g_spart[blockIdx.x][m0 + tid] = v;
    }
}

// ---------------------------------------------------------------------------
// Kernel 2a/2b: mean of x over T per batch (deterministic two-stage)
// ---------------------------------------------------------------------------
__global__ void k_xmean_part(const float* __restrict__ x)
{
    int b = blockIdx.x, ch = blockIdx.y, d = threadIdx.x;
    const float* base = x + ((size_t)b * TT + ch * 256) * DIN + d;
    float acc = 0.f;
    for (int t = 0; t < 256; t++) acc += base[(size_t)t * DIN];
    g_xpart[(ch * BB + b) * DIN + d] = acc;
}
__global__ void k_xmean_fin()
{
    int b = blockIdx.x, d = threadIdx.x;
    float acc = 0.f;
    for (int ch = 0; ch < 16; ch++) acc += g_xpart[(ch * BB + b) * DIN + d];
    g_xmean[b * DIN + d] = acc * (1.0f / TT);
}

// ---------------------------------------------------------------------------
// Kernel 3: fused sal-finalize + PGD selector (warm-started Newton tau,
// 1-sync block reduces), y_star out, mean_sal, exact top-32.
// ---------------------------------------------------------------------------
__global__ __launch_bounds__(1024) void k_selector(
    const float* __restrict__ b_sal, float* __restrict__ d_out)
{
    __shared__ float ysA[TT];
    __shared__ float ysB[TT];
    __shared__ float redS[2][32], redC[2][32];
    __shared__ float redT[2][32];
    __shared__ int   redi[2][32];

    const int b = blockIdx.x;
    const int tid = threadIdx.x;
    const int lane = tid & 31, wid = tid >> 5;
    const int i0 = tid * 4;

    float4 p0 = *(const float4*)&g_spart[0][b * TT + i0];
    float4 p1 = *(const float4*)&g_spart[1][b * TT + i0];
    float4 p2 = *(const float4*)&g_spart[2][b * TT + i0];
    float4 p3 = *(const float4*)&g_spart[3][b * TT + i0];
    const float bs = b_sal[0];
    float s[4];
    {
        float z0 = ((p0.x + p1.x) + p2.x) + p3.x + bs;
        float z1 = ((p0.y + p1.y) + p2.y) + p3.y + bs;
        float z2 = ((p0.z + p1.z) + p2.z) + p3.z + bs;
        float z3 = ((p0.w + p1.w) + p2.w) + p3.w + bs;
        s[0] = fmaxf(z0, 0.f) + log1pf(expf(-fabsf(z0)));
        s[1] = fmaxf(z1, 0.f) + log1pf(expf(-fabsf(z1)));
        s[2] = fmaxf(z2, 0.f) + log1pf(expf(-fabsf(z2)));
        s[3] = fmaxf(z3, 0.f) + log1pf(expf(-fabsf(z3)));
    }
    *(float4*)&g_sal[b * TT + i0] = make_float4(s[0], s[1], s[2], s[3]);

    float y[4] = {0.0078125f, 0.0078125f, 0.0078125f, 0.0078125f};
    ysA[i0] = y[0]; ysA[i0 + 1] = y[1]; ysA[i0 + 2] = y[2]; ysA[i0 + 3] = y[3];
    __syncthreads();

    float tau_prev = 0.f;
    for (int step = 0; step < PGD_STEPS; step++) {
        const float* rd = (step & 1) ? ysB : ysA;
        float*       wr = (step & 1) ? ysA : ysB;
        float l1 = (i0 > 0) ? rd[i0 - 1] : 0.f;
        float l2 = (i0 > 0) ? rd[i0 - 2] : 0.f;
        float r1 = (i0 + 4 < TT) ? rd[i0 + 4] : 0.f;
        float r2 = (i0 + 4 < TT) ? rd[i0 + 5] : 0.f;
        float nb[4];
        nb[0] = ((y[1] + l1) + y[2]) + l2;
        nb[1] = ((y[2] + y[0]) + y[3]) + l1;
        nb[2] = ((y[3] + y[1]) + r1) + y[0];
        nb[3] = ((r1 + y[2]) + r2) + y[1];

        float z[4];
#pragma unroll
        for (int q = 0; q < 4; q++) {
            float g = (s[q] - y[q]) - 0.5f * nb[q];
            z[q] = fminf(fmaxf(y[q] + 0.1f * g, 0.f), 1.f);
        }

        float tau = tau_prev;
        for (int it = 0; it < 24; it++) {
            const int p = it & 1;
            float ls = 0.f, lc = 0.f;
#pragma unroll
            for (int q = 0; q < 4; q++)
                if (z[q] > tau) { ls += z[q]; lc += 1.f; }
#pragma unroll
            for (int o = 16; o; o >>= 1) {
                ls += __shfl_xor_sync(0xffffffffu, ls, o);
                lc += __shfl_xor_sync(0xffffffffu, lc, o);
            }
            if (lane == 0) { redS[p][wid] = ls; redC[p][wid] = lc; }
            __syncthreads();
            float S = redS[p][lane], C = redC[p][lane];
#pragma unroll
            for (int o = 16; o; o >>= 1) {
                S += __shfl_xor_sync(0xffffffffu, S, o);
                C += __shfl_xor_sync(0xffffffffu, C, o);
            }
            float tnew = (C >= 1.f) ? fmaxf((S - 32.f) / C, 0.f) : 0.f;
            if (tnew == tau) break;
            tau = tnew;
        }
        tau_prev = tau;
#pragma unroll
        for (int q = 0; q < 4; q++)
            y[q] = fminf(fmaxf(z[q] - tau, 0.f), 1.f);
        wr[i0] = y[0]; wr[i0 + 1] = y[1]; wr[i0 + 2] = y[2]; wr[i0 + 3] = y[3];
        __syncthreads();
    }

    float* outY = d_out + (size_t)BB * KSEL * DMODEL + (size_t)b * TT;
    *(float4*)&outY[i0] = make_float4(y[0], y[1], y[2], y[3]);

    {
        float ms = ((s[0] + s[1]) + s[2]) + s[3];
#pragma unroll
        for (int o = 16; o; o >>= 1) ms += __shfl_xor_sync(0xffffffffu, ms, o);
        if (lane == 0) redS[0][wid] = ms;
        __syncthreads();
        if (tid < 32) {
            float v = redS[0][lane];
#pragma unroll
            for (int o = 16; o; o >>= 1) v += __shfl_xor_sync(0xffffffffu, v, o);
            if (lane == 0) g_msal[b] = v * (1.0f / TT);
        }
        __syncthreads();
    }

    float mval[4] = {y[0], y[1], y[2], y[3]};
    for (int sel = 0; sel < KSEL; sel++) {
        const int p = sel & 1;
        float bv = -1.f; int bi = TT;
#pragma unroll
        for (int q = 0; q < 4; q++)
            if (mval[q] > bv) { bv = mval[q]; bi = i0 + q; }
#pragma unroll
        for (int o = 16; o; o >>= 1) {
            float ov = __shfl_xor_sync(0xffffffffu, bv, o);
            int   oi = __shfl_xor_sync(0xffffffffu, bi, o);
            if (ov > bv || (ov == bv && oi < bi)) { bv = ov; bi = oi; }
        }
        if (lane == 0) { redT[p][wid] = bv; redi[p][wid] = bi; }
        __syncthreads();
        bv = redT[p][lane]; bi = redi[p][lane];
#pragma unroll
        for (int o = 16; o; o >>= 1) {
            float ov = __shfl_xor_sync(0xffffffffu, bv, o);
            int   oi = __shfl_xor_sync(0xffffffffu, bi, o);
            if (ov > bv || (ov == bv && oi < bi)) { bv = ov; bi = oi; }
        }
        if (tid == 0) g_topidx[b * KSEL + sel] = bi;
        if ((bi >> 2) == tid) mval[bi & 3] = -1.f;
    }
}

// ---------------------------------------------------------------------------
// Kernel 4: gather -> anchor vector -> lift (259->64) -> project (64->1024)
// ---------------------------------------------------------------------------
__global__ __launch_bounds__(256) void k_tokens(
    const float* __restrict__ x, const float* __restrict__ mu,
    const float* __restrict__ sigma, const float* __restrict__ W_lift,
    const float* __restrict__ b_lift, const float* __restrict__ W_proj,
    const float* __restrict__ b_proj, float* __restrict__ out)
{
    __shared__ float u[AD];
    __shared__ float lf[KLIFT];
    const int b = blockIdx.x, j = blockIdx.y;
    const int tid = threadIdx.x;
    const int idx = g_topidx[b * KSEL + j];

    {
        float v = x[((size_t)b * TT + idx) * DIN + tid] - g_xmean[b * DIN + tid];
        u[tid] = (v - mu[tid]) / sigma[tid];
    }
    if (tid == 0) {
        float sali = g_sal[b * TT + idx];
        float ms = g_msal[b];
        u[256] = ((sali - ms) - mu[256]) / sigma[256];
        float tn = (float)idx * (1.0f / 4096.0f);
        u[257] = ((tn - 0.4998779296875f) - mu[257]) / sigma[257];
        float ds = (idx == 0) ? 0.f : (sali - g_sal[b * TT + idx - 1]);
        float mds = (g_sal[b * TT + TT - 1] - g_sal[b * TT]) * (1.0f / 4096.0f);
        u[258] = ((ds - mds) - mu[258]) / sigma[258];
    }
    __syncthreads();

    if (tid < KLIFT) {
        float acc = b_lift[tid];
        for (int d = 0; d < AD; d++)
            acc = fmaf(u[d], W_lift[d * KLIFT + tid], acc);
        lf[tid] = acc;
    }
    __syncthreads();

    float* o = out + ((size_t)(b * KSEL + j)) * DMODEL;
    for (int m = tid; m < DMODEL; m += 256) {
        float acc = b_proj[m];
#pragma unroll
        for (int k = 0; k < KLIFT; k++)
            acc = fmaf(lf[k], W_proj[k * DMODEL + m], acc);
        o[m] = acc;
    }
}

// ---------------------------------------------------------------------------
extern "C" void kernel_launch(void* const* d_in, const int* in_sizes, int n_in,
                              void* d_out, int out_size)
{
    const float* x      = (const float*)d_in[0];
    const float* W1     = (const float*)d_in[1];
    const float* b1     = (const float*)d_in[2];
    const float* w_sal  = (const float*)d_in[5];
    const float* b_sal  = (const float*)d_in[6];
    const float* mu     = (const float*)d_in[7];
    const float* sigma  = (const float*)d_in[8];
    const float* W_lift = (const float*)d_in[9];
    const float* b_lift = (const float*)d_in[10];
    const float* W_proj = (const float*)d_in[11];
    const float* b_proj = (const float*)d_in[12];
    float* out = (float*)d_out;

    static cudaStream_t s2 = []() {
        cudaStream_t s; cudaStreamCreateWithFlags(&s, cudaStreamNonBlocking); return s;
    }();
    static cudaEvent_t evF = []() {
        cudaEvent_t e; cudaEventCreateWithFlags(&e, cudaEventDisableTiming); return e;
    }();
    static cudaEvent_t evJ = []() {
        cudaEvent_t e; cudaEventCreateWithFlags(&e, cudaEventDisableTiming); return e;
    }();

    cudaEventRecord(evF, 0);
    cudaStreamWaitEvent(s2, evF, 0);
    k_xmean_part<<<dim3(BB, 16), 256, 0, s2>>>(x);
    k_xmean_fin<<<BB, 256, 0, s2>>>();
    cudaEventRecord(evJ, s2);

    k_convert_w<<<dim3(64, 16), 32>>>(W1);
    k_gemm_part<<<dim3(4, 1024), 256>>>(x, b1, w_sal);
    k_selector<<<BB, 1024>>>(b_sal, out);

    cudaStreamWaitEvent(0, evJ, 0);
    k_tokens<<<dim3(BB, KSEL), 256>>>(x, mu, sigma, W_lift, b_lift, W_proj, b_proj, out);
}